// round 2
// baseline (speedup 1.0000x reference)
#include <cuda_runtime.h>

// LSTMClassifier: B=2048, T=256, F=64, H=128.
// Per-batch-row recurrence is independent -> each block owns ROWS batch rows,
// loops all T steps locally. No inter-block sync needed.

#define T_STEPS 256
#define FDIM    64
#define HDIM    128
#define KTOT    192          // F + H
#define GDIM    512          // 4H gate columns
#define ROWS    16           // batch rows per block
#define KT      12           // k-tile staged in smem
#define NTILES  16           // 192 / 12
#define NBLOCKS (2048 / ROWS)

// Packed fused weights: g_Wt[k][4*c + q] = (k<F ? W_ih : W_hh)[q*H + c][k or k-F]
__device__ float g_Wt[KTOT * GDIM];
__device__ float g_b4[GDIM];

__global__ void pack_kernel(const float* __restrict__ Wih,
                            const float* __restrict__ Whh,
                            const float* __restrict__ bih,
                            const float* __restrict__ bhh) {
    int idx = blockIdx.x * blockDim.x + threadIdx.x;
    if (idx < KTOT * GDIM) {
        int k = idx >> 9;          // 0..191
        int j = idx & 511;
        int c = j >> 2, q = j & 3;
        int row = q * HDIM + c;    // original gate row (PyTorch order i,f,g,o)
        g_Wt[idx] = (k < FDIM) ? Wih[row * FDIM + k]
                               : Whh[row * HDIM + (k - FDIM)];
    }
    if (idx < GDIM) {
        int c = idx >> 2, q = idx & 3;
        int row = q * HDIM + c;
        g_b4[idx] = bih[row] + bhh[row];
    }
}

__device__ __forceinline__ float sigm(float x) {
    return 1.0f / (1.0f + __expf(-x));
}
__device__ __forceinline__ float tanh_fast(float x) {
    x = fminf(fmaxf(x, -15.0f), 15.0f);
    float e = __expf(2.0f * x);
    return __fdividef(e - 1.0f, e + 1.0f);
}

__global__ __launch_bounds__(256, 1) void lstm_kernel(
    const float* __restrict__ x,
    const float* __restrict__ W1, const float* __restrict__ b1,
    const float* __restrict__ W2, const float* __restrict__ b2,
    float* __restrict__ out)
{
    // inS[k][r]: k<64 = x features of step t, k>=64 = h (transposed, row-minor)
    __shared__ float inS[KTOT][20];      // stride 20 floats -> 16B-aligned rows
    __shared__ float wS[KT][516];        // k-tile of packed weights, padded
    __shared__ float zS[ROWS][32];

    const int tid = threadIdx.x;
    const int b0  = blockIdx.x * ROWS;
    const int rg  = tid >> 7;            // 0..1 : row group (8 rows each)
    const int c   = tid & 127;           // hidden unit owned by this thread

    const float4 breg = *(const float4*)&g_b4[c * 4];

    float creg[8];
#pragma unroll
    for (int i = 0; i < 8; i++) creg[i] = 0.0f;

    // zero the h region of inS (initial hidden state = 0)
    for (int i = tid; i < HDIM * 20; i += 256)
        inS[FDIM + i / 20][i % 20] = 0.0f;

    const float* xbase = x + (long)b0 * T_STEPS * FDIM;

    for (int t = 0; t < T_STEPS; t++) {
        // ---- load x tile for this step, transposed into inS[k][r] ----
        {
            int r  = tid >> 4;           // 0..15
            int kq = (tid & 15) * 4;     // 0..60
            float4 xv = *(const float4*)&xbase[((long)r * T_STEPS + t) * FDIM + kq];
            inS[kq + 0][r] = xv.x;
            inS[kq + 1][r] = xv.y;
            inS[kq + 2][r] = xv.z;
            inS[kq + 3][r] = xv.w;
        }

        float4 acc[8];
#pragma unroll
        for (int rr = 0; rr < 8; rr++) acc[rr] = breg;

        // ---- gates GEMM: acc[rr][q] = b + sum_k in[r][k] * Wt[k][4c+q] ----
#pragma unroll 1
        for (int tile = 0; tile < NTILES; tile++) {
            const int k0 = tile * KT;
            __syncthreads();             // prev tile consumed (also orders x/h writes)
            // stage 12x512 weight slab: coalesced f4 loads, conflict-free f4 stores
#pragma unroll
            for (int w = 0; w < 6; w++) {
                int fi = tid + w * 256;          // 0..1535
                int kk = fi >> 7;                // 0..11
                int jj = (fi & 127) * 4;         // 0..508
                *(float4*)&wS[kk][jj] =
                    *(const float4*)&g_Wt[(k0 + kk) * GDIM + jj];
            }
            __syncthreads();
#pragma unroll
            for (int kk = 0; kk < KT; kk++) {
                float4 w4 = *(const float4*)&wS[kk][c * 4];
                float4 ha = *(const float4*)&inS[k0 + kk][rg * 8];      // rows 0..3
                float4 hb = *(const float4*)&inS[k0 + kk][rg * 8 + 4];  // rows 4..7
                acc[0].x += ha.x * w4.x; acc[0].y += ha.x * w4.y;
                acc[0].z += ha.x * w4.z; acc[0].w += ha.x * w4.w;
                acc[1].x += ha.y * w4.x; acc[1].y += ha.y * w4.y;
                acc[1].z += ha.y * w4.z; acc[1].w += ha.y * w4.w;
                acc[2].x += ha.z * w4.x; acc[2].y += ha.z * w4.y;
                acc[2].z += ha.z * w4.z; acc[2].w += ha.z * w4.w;
                acc[3].x += ha.w * w4.x; acc[3].y += ha.w * w4.y;
                acc[3].z += ha.w * w4.z; acc[3].w += ha.w * w4.w;
                acc[4].x += hb.x * w4.x; acc[4].y += hb.x * w4.y;
                acc[4].z += hb.x * w4.z; acc[4].w += hb.x * w4.w;
                acc[5].x += hb.y * w4.x; acc[5].y += hb.y * w4.y;
                acc[5].z += hb.y * w4.z; acc[5].w += hb.y * w4.w;
                acc[6].x += hb.z * w4.x; acc[6].y += hb.z * w4.y;
                acc[6].z += hb.z * w4.z; acc[6].w += hb.z * w4.w;
                acc[7].x += hb.w * w4.x; acc[7].y += hb.w * w4.y;
                acc[7].z += hb.w * w4.z; acc[7].w += hb.w * w4.w;
            }
        }
        __syncthreads();                 // all reads of inS done before h rewrite

        // ---- pointwise LSTM cell update; c in regs, h -> smem ----
#pragma unroll
        for (int rr = 0; rr < 8; rr++) {
            float ig = sigm(acc[rr].x);
            float fg = sigm(acc[rr].y);
            float gg = tanh_fast(acc[rr].z);
            float og = sigm(acc[rr].w);
            creg[rr] = fg * creg[rr] + ig * gg;
            inS[FDIM + c][rg * 8 + rr] = og * tanh_fast(creg[rr]);
        }
        // next iter: x-load writes inS[k<64] (disjoint), tile-0 sync publishes h
    }
    __syncthreads();

    // ---- head: Linear(128,32) -> ReLU -> Linear(32,1) -> Sigmoid ----
    {
        int m  = tid & 31;               // 0..31 : hidden unit of layer 1
        int r0 = tid >> 5;               // 0..7
#pragma unroll
        for (int h = 0; h < 2; h++) {
            int r = r0 + h * 8;
            float z = b1[m];
            for (int k = 0; k < HDIM; k++)
                z += inS[FDIM + k][r] * W1[m * HDIM + k];
            zS[r][m] = fmaxf(z, 0.0f);
        }
    }
    __syncthreads();
    if (tid < ROWS) {
        float s = b2[0];
#pragma unroll
        for (int m = 0; m < 32; m++) s += zS[tid][m] * W2[m];
        out[b0 + tid] = sigm(s);
    }
}

extern "C" void kernel_launch(void* const* d_in, const int* in_sizes, int n_in,
                              void* d_out, int out_size) {
    const float* x   = (const float*)d_in[0];
    const float* Wih = (const float*)d_in[1];
    const float* Whh = (const float*)d_in[2];
    const float* bih = (const float*)d_in[3];
    const float* bhh = (const float*)d_in[4];
    const float* W1  = (const float*)d_in[5];
    const float* b1  = (const float*)d_in[6];
    const float* W2  = (const float*)d_in[7];
    const float* b2  = (const float*)d_in[8];
    float* out = (float*)d_out;

    pack_kernel<<<(KTOT * GDIM + 255) / 256, 256>>>(Wih, Whh, bih, bhh);
    lstm_kernel<<<NBLOCKS, 256>>>(x, W1, b1, W2, b2, out);
}

// round 4
// speedup vs baseline: 8.0377x; 8.0377x over previous
#include <cuda_runtime.h>
#include <cuda_fp16.h>
#include <cstdint>

// LSTMClassifier B=2048,T=256,F=64,H=128 via mma.sync (HMMA) on sm_103.
// Per block: 16 batch rows. Per step: D[512 gates,16] = W[512,192] @ in^T.
// Weights fp16 resident in smem; accumulators + cell state in registers.

#define T_STEPS 256
#define FDIM 64
#define HDIM 128
#define ROWS 16
#define NBLOCKS 128
#define NTHREADS 256

// smem byte offsets
#define AW_OFF  0                         // 512x192 fp16 A tiles = 196608 B
#define INT_OFF 196608                    // in^T: 192 rows(k) x 32B(16 fp16 cols)
#define HS_OFF  (INT_OFF + 6144)          // final h fp32 [128 u][16 r] = 8192 B
#define SMEM_TOTAL (HS_OFF + 8192)        // 210944 B

__device__ __forceinline__ uint32_t smem_u32(const void* p) {
    uint32_t a;
    asm("{ .reg .u64 t; cvta.to.shared.u64 t, %1; cvt.u32.u64 %0, t; }" : "=r"(a) : "l"(p));
    return a;
}

#define LDSM_X4(r0, r1, r2, r3, a) \
    asm volatile("ldmatrix.sync.aligned.m8n8.x4.shared.b16 {%0,%1,%2,%3}, [%4];" \
                 : "=r"(r0), "=r"(r1), "=r"(r2), "=r"(r3) : "r"(a))

#define LDSM_X4_T(r0, r1, r2, r3, a) \
    asm volatile("ldmatrix.sync.aligned.m8n8.x4.trans.shared.b16 {%0,%1,%2,%3}, [%4];" \
                 : "=r"(r0), "=r"(r1), "=r"(r2), "=r"(r3) : "r"(a))

#define MMA16816(d, a0, a1, a2, a3, b0, b1) \
    asm volatile("mma.sync.aligned.m16n8k16.row.col.f32.f16.f16.f32 " \
                 "{%0,%1,%2,%3}, {%4,%5,%6,%7}, {%8,%9}, {%0,%1,%2,%3};" \
                 : "+f"((d)[0]), "+f"((d)[1]), "+f"((d)[2]), "+f"((d)[3]) \
                 : "r"(a0), "r"(a1), "r"(a2), "r"(a3), "r"(b0), "r"(b1))

__device__ __forceinline__ float sigm(float v) {
    float e = __expf(-v);
    return __fdividef(1.0f, 1.0f + e);
}
__device__ __forceinline__ float tanh_e(float v) {
    float a = fabsf(v);
    float e = __expf(-2.0f * a);
    float r = __fdividef(1.0f - e, 1.0f + e);
    return copysignf(r, v);
}

__global__ __launch_bounds__(NTHREADS, 1) void lstm_mma_kernel(
    const float* __restrict__ x,
    const float* __restrict__ Wih, const float* __restrict__ Whh,
    const float* __restrict__ bih, const float* __restrict__ bhh,
    const float* __restrict__ W1, const float* __restrict__ b1,
    const float* __restrict__ W2, const float* __restrict__ b2,
    float* __restrict__ out)
{
    extern __shared__ char smem[];
    const uint32_t sb = smem_u32(smem);
    const int tid  = threadIdx.x;
    const int wid  = tid >> 5;
    const int lane = tid & 31;
    const int b0   = blockIdx.x * ROWS;

    // ---- convert W_ih | W_hh (fp32) -> fp16 swizzled 16x16 tiles in smem ----
    // Tile (wid_o, q, kt): base = ((wid_o*4+q)*12+kt)*512. Row j (unit), col kl.
    // Swizzle: halfpair (j, kl even) stored at j*32 + ((kl>>3)^((j>>2)&1))*16 + (kl&7)*2.
    for (int i = tid; i < 512 * 96; i += NTHREADS) {
        int row = i / 96;                 // 0..511 = q*128 + u
        int kp  = (i - row * 96) * 2;     // 0..190 even
        int q = row >> 7, u = row & 127;
        int wo = u >> 4, j = u & 15;
        int kt = kp >> 4, kl = kp & 15;
        float2 v;
        if (kp < FDIM) v = *(const float2*)(Wih + row * FDIM + kp);
        else           v = *(const float2*)(Whh + row * HDIM + (kp - FDIM));
        uint32_t addr = (uint32_t)(((wo * 4 + q) * 12 + kt) * 512
                        + j * 32 + (((kl >> 3) ^ ((j >> 2) & 1)) << 4) + (kl & 7) * 2);
        *(__half2*)(smem + AW_OFF + addr) = __floats2half2_rn(v.x, v.y);
    }
    // zero h region of in^T (rows 64..191)
    for (int i = tid; i < 1024; i += NTHREADS)
        ((uint32_t*)(smem + INT_OFF + 2048))[i] = 0;

    // ---- per-thread constants ----
    const int s = lane >> 3, jj = lane & 7;
    // A ldmatrix lane address offset (within a tile)
    const int Ja = ((s & 1) << 3) + jj;
    const uint32_t a_base = sb + AW_OFF + wid * 24576
        + (uint32_t)(Ja * 32 + ((((s >> 1)) ^ ((Ja >> 2) & 1)) << 4));
    // B ldmatrix lane address (within k-tile 0)
    const int kb = ((s & 1) << 3) + jj;
    const uint32_t b_base = sb + INT_OFF
        + (uint32_t)(kb * 32 + ((((s >> 1)) ^ ((kb >> 2) & 1)) << 4));

    const int g  = lane >> 2;             // d-frag row (0..7)
    const int cq = lane & 3;              // d-frag col pair selector
    const int ug = wid * 16 + g;          // unit for row-half 0 (+8 for half 1)

    float bL[4], bH[4];
#pragma unroll
    for (int q = 0; q < 4; q++) {
        bL[q] = bih[q * HDIM + ug]     + bhh[q * HDIM + ug];
        bH[q] = bih[q * HDIM + ug + 8] + bhh[q * HDIM + ug + 8];
    }

    // h write addresses: (nt, rh) -> row k = 64+ug+rh*8, chunk = nt ^ ((g>>2)&1)
    uint32_t h_addr[2][2];
#pragma unroll
    for (int nt = 0; nt < 2; nt++)
#pragma unroll
        for (int rh = 0; rh < 2; rh++)
            h_addr[nt][rh] = sb + INT_OFF
                + (uint32_t)((64 + ug + rh * 8) * 32
                + ((nt ^ ((g >> 2) & 1)) << 4) + cq * 4);

    // x publish: this thread covers batch row xr_, features xch*4..+3
    const int xrow = tid >> 4, xch = tid & 15;
    const float* xptr = x + ((size_t)(b0 + xrow) * T_STEPS + 0) * FDIM + xch * 4;
    const uint32_t x_addr = sb + INT_OFF
        + (uint32_t)((xch * 4) * 32 + (((xrow >> 3) ^ (xch & 1)) << 4) + (xrow & 7) * 2);

    float cs[8];
#pragma unroll
    for (int i = 0; i < 8; i++) cs[i] = 0.0f;

    float4 xr = *(const float4*)xptr;     // t = 0

    for (int t = 0; t < T_STEPS; t++) {
        // ---- publish x_t (fp16, swizzled) ----
        *(__half*)(smem + (x_addr - sb) + 0 * 32)  = __float2half_rn(xr.x);
        *(__half*)(smem + (x_addr - sb) + 1 * 32)  = __float2half_rn(xr.y);
        *(__half*)(smem + (x_addr - sb) + 2 * 32)  = __float2half_rn(xr.z);
        *(__half*)(smem + (x_addr - sb) + 3 * 32)  = __float2half_rn(xr.w);
        __syncthreads();                  // x + h(prev) visible to all warps

        // ---- init D with bias ----
        float D[4][8];
#pragma unroll
        for (int q = 0; q < 4; q++) {
#pragma unroll
            for (int nt = 0; nt < 2; nt++) {
                D[q][nt * 4 + 0] = bL[q]; D[q][nt * 4 + 1] = bL[q];
                D[q][nt * 4 + 2] = bH[q]; D[q][nt * 4 + 3] = bH[q];
            }
        }

        // ---- 12 k-tiles x 4 gate m-tiles x 2 n-tiles ----
#pragma unroll
        for (int kt = 0; kt < 12; kt++) {
            uint32_t v0, v1, v2, v3;
            LDSM_X4_T(v0, v1, v2, v3, b_base + kt * 512);
#pragma unroll
            for (int q = 0; q < 4; q++) {
                uint32_t a0, a1, a2, a3;
                LDSM_X4(a0, a1, a2, a3, a_base + (q * 12 + kt) * 512);
                MMA16816(&D[q][0], a0, a1, a2, a3, v0, v1);
                MMA16816(&D[q][4], a0, a1, a2, a3, v2, v3);
            }
        }
        __syncthreads();                  // all reads done before h/x rewrite

        // ---- prefetch next x ----
        if (t + 1 < T_STEPS) xr = *(const float4*)(xptr + (size_t)(t + 1) * FDIM);

        // ---- cell update: 2 row-halves x 2 n-tiles x 2 cols ----
#pragma unroll
        for (int nt = 0; nt < 2; nt++) {
#pragma unroll
            for (int rh = 0; rh < 2; rh++) {
                float h0, h1;
#pragma unroll
                for (int ci = 0; ci < 2; ci++) {
                    int di = rh * 2 + ci;
                    float gi = sigm(D[0][nt * 4 + di]);
                    float gf = sigm(D[1][nt * 4 + di]);
                    float gg = tanh_e(D[2][nt * 4 + di]);
                    float go = sigm(D[3][nt * 4 + di]);
                    int sidx = nt * 4 + di;
                    cs[sidx] = gf * cs[sidx] + gi * gg;
                    float h = go * tanh_e(cs[sidx]);
                    if (ci == 0) h0 = h; else h1 = h;
                    if (t == T_STEPS - 1) {
                        int u = ug + rh * 8;
                        int r = nt * 8 + cq * 2 + ci;
                        *(float*)(smem + HS_OFF + (u * 16 + r) * 4) = h;
                    }
                }
                *(__half2*)(smem + (h_addr[nt][rh] - sb)) =
                    __floats2half2_rn(h0, h1);
            }
        }
    }
    __syncthreads();

    // ---- head: Linear(128,32) -> ReLU -> Linear(32,1) -> Sigmoid ----
    float* W1t = (float*)(smem + AW_OFF);           // reuse weight region
    float* zS  = (float*)(smem + AW_OFF + 16384);   // 16x32 fp32
    const float* hs = (const float*)(smem + HS_OFF);
    for (int i = tid; i < 32 * HDIM; i += NTHREADS) {
        int m = i >> 7, k = i & 127;
        W1t[k * 32 + m] = W1[i];
    }
    __syncthreads();
    {
        int m = tid & 31, r0 = tid >> 5;
#pragma unroll
        for (int hh = 0; hh < 2; hh++) {
            int r = r0 + hh * 8;
            float z = b1[m];
            for (int k = 0; k < HDIM; k++)
                z += hs[k * 16 + r] * W1t[k * 32 + m];
            zS[r * 32 + m] = fmaxf(z, 0.0f);
        }
    }
    __syncthreads();
    if (tid < ROWS) {
        float ssum = b2[0];
#pragma unroll
        for (int mm = 0; mm < 32; mm++) ssum += zS[tid * 32 + mm] * W2[mm];
        out[b0 + tid] = sigm(ssum);
    }
}

extern "C" void kernel_launch(void* const* d_in, const int* in_sizes, int n_in,
                              void* d_out, int out_size) {
    (void)in_sizes; (void)n_in; (void)out_size;
    const float* x   = (const float*)d_in[0];
    const float* Wih = (const float*)d_in[1];
    const float* Whh = (const float*)d_in[2];
    const float* bih = (const float*)d_in[3];
    const float* bhh = (const float*)d_in[4];
    const float* W1  = (const float*)d_in[5];
    const float* b1  = (const float*)d_in[6];
    const float* W2  = (const float*)d_in[7];
    const float* b2  = (const float*)d_in[8];
    float* out = (float*)d_out;

    cudaFuncSetAttribute(lstm_mma_kernel,
                         cudaFuncAttributeMaxDynamicSharedMemorySize, SMEM_TOTAL);
    lstm_mma_kernel<<<NBLOCKS, NTHREADS, SMEM_TOTAL>>>(
        x, Wih, Whh, bih, bhh, W1, b1, W2, b2, out);
}